// round 11
// baseline (speedup 1.0000x reference)
#include <cuda_runtime.h>
#include <cuda_bf16.h>
#include <cstdint>

#define NUM_TAGS 48
#define SEQ_LEN  512
#define BATCH    1024
#define CHUNK    8
#define NCHUNK   (SEQ_LEN / CHUNK)   // 64

__device__ float    g_nll[BATCH];
__device__ unsigned g_count = 0;

// ---- packed f32x2 helpers ----------------------------------------------------
__device__ __forceinline__ void fma2(uint64_t& d, uint64_t a, uint64_t b) {
    asm("fma.rn.f32x2 %0, %1, %2, %0;" : "+l"(d) : "l"(a), "l"(b));
}
__device__ __forceinline__ uint64_t add2(uint64_t a, uint64_t b) {
    uint64_t d;
    asm("add.rn.f32x2 %0, %1, %2;" : "=l"(d) : "l"(a), "l"(b));
    return d;
}
__device__ __forceinline__ uint64_t pack2(float lo, float hi) {
    uint64_t d;
    asm("mov.b64 %0, {%1, %2};" : "=l"(d) : "f"(lo), "f"(hi));
    return d;
}
__device__ __forceinline__ float lo2(uint64_t v) { return __uint_as_float((uint32_t)v); }
__device__ __forceinline__ float hi2(uint64_t v) { return __uint_as_float((uint32_t)(v >> 32)); }

// one u32 holding two bf16 -> f32x2 pair (bf16 is truncated fp32: val = bits<<16)
__device__ __forceinline__ uint64_t bf2_to_f32x2(uint32_t u) {
    uint32_t lo = u << 16;
    uint32_t hi = u & 0xFFFF0000u;
    uint64_t d;
    asm("mov.b64 %0, {%1, %2};" : "=l"(d) : "r"(lo), "r"(hi));
    return d;
}
__device__ __forceinline__ uint16_t f2bf(float f) {
    uint16_t r;
    asm("cvt.rn.bf16.f32 %0, %1;" : "=h"(r) : "f"(f));
    return r;
}

__device__ __forceinline__ void cp16(uint32_t saddr, const void* g) {
    asm volatile("cp.async.cg.shared.global [%0], [%1], 16;" :: "r"(saddr), "l"(g));
}

// One warp (one CTA) per batch element. Alpha lives in shared as 48 x bf16 =
// 96 B (ONE 128-B line): loads are 3 single-line broadcast LDS.128, stores are
// 3 STS.16. FMA runs in fp32 (E fp32, alpha unpacked via ALU shifts). Lazy
// per-chunk renorm; no WARPSYNC in the fast-path step loop (full-mask shfl
// anchors convergence; pair lanes store bit-identical duplicates).
__global__ __launch_bounds__(32)
void crf_fused_kernel(const float* __restrict__ emissions,
                      const float* __restrict__ transitions,
                      const int*   __restrict__ tags,
                      const int*   __restrict__ mask,
                      float*       __restrict__ out)
{
    const int lane = threadIdx.x;
    const int b    = blockIdx.x;
    const int h    = lane >> 4;     // K half: rows [24h, 24h+24)
    const int q    = lane & 15;     // owned output triple {3q,3q+1,3q+2}
    const int j0   = 3 * q;

    __shared__ __align__(128) uint32_t swb16[2][32];          // 48 bf16 + pad, per buffer
    __shared__ __align__(16)  float sem[3][CHUNK * NUM_TAGS]; // emission chunks (3-deep)
    __shared__ int stags[SEQ_LEN];
    __shared__ int smask[SEQ_LEN];

    const float* em_b   = emissions + (size_t)b * SEQ_LEN * NUM_TAGS;
    const int*   tags_b = tags + b * SEQ_LEN;
    const int*   mask_b = mask + b * SEQ_LEN;

    // --- stage emission chunks 0 and 1 ------------------------------------------
    #pragma unroll
    for (int pc = 0; pc < 2; pc++) {
        uint32_t dst = (uint32_t)__cvta_generic_to_shared(&sem[pc][0]);
        const float* src = em_b + (size_t)pc * CHUNK * NUM_TAGS;
        #pragma unroll
        for (int r = 0; r < 3; r++)
            cp16(dst + lane * 16 + r * 512, src + lane * 4 + r * 128);
        asm volatile("cp.async.commit_group;");
    }

    // --- tags / mask to shared ------------------------------------------------------
    #pragma unroll
    for (int r = 0; r < 4; r++) {
        ((int4*)stags)[lane + 32 * r] = ((const int4*)tags_b)[lane + 32 * r];
        ((int4*)smask)[lane + 32 * r] = ((const int4*)mask_b)[lane + 32 * r];
    }

    // --- E = exp(T): f32x2 pairs, 3 owned columns x 24 input rows (this K half) -----
    const int i0 = 24 * h;
    uint64_t Ec[36];
    #pragma unroll
    for (int c = 0; c < 3; c++)
        #pragma unroll
        for (int k = 0; k < 12; k++)
            Ec[c * 12 + k] = pack2(__expf(transitions[(i0 + 2 * k    ) * NUM_TAGS + j0 + c]),
                                   __expf(transitions[(i0 + 2 * k + 1) * NUM_TAGS + j0 + c]));

    // --- init alphas: only tag 0 live (bf16(1.0) = 0x3F80 in low half of word 0) -----
    float w0 = (q == 0) ? 1.0f : 0.0f;
    float w1 = 0.0f, w2 = 0.0f;
    if (lane < 24) swb16[0][lane] = (lane == 0) ? 0x00003F80u : 0u;
    __syncwarp();

    // --- gold-path score (overlaps staged-chunk latency) ------------------------------
    float sc = 0.0f;
    #pragma unroll 4
    for (int t = 1 + lane; t < SEQ_LEN; t += 32) {
        int tc = stags[t], tp = stags[t - 1];
        if (smask[t])
            sc += em_b[(size_t)t * NUM_TAGS + tc] + transitions[tp * NUM_TAGS + tc];
    }
    #pragma unroll
    for (int off = 16; off; off >>= 1)
        sc += __shfl_xor_sync(0xffffffffu, sc, off);

    // --- forward recursion: 64 chunks x 8 steps ----------------------------------------
    float C = 0.0f;
    float carry_inv = 1.0f;   // pending renorm scale (exact once logged)

    for (int c = 0; c < NCHUNK; c++) {
        if (c + 2 < NCHUNK) {
            uint32_t dst = (uint32_t)__cvta_generic_to_shared(&sem[(c + 2) % 3][0]);
            const float* src = em_b + (size_t)(c + 2) * CHUNK * NUM_TAGS;
            #pragma unroll
            for (int r = 0; r < 3; r++)
                cp16(dst + lane * 16 + r * 512, src + lane * 4 + r * 128);
        }
        asm volatile("cp.async.commit_group;");
        asm volatile("cp.async.wait_group 2;");   // chunk c resident
        __syncwarp();

        const float* eb = sem[c % 3];

        // hoist emission exps (off the recurrence chain)
        float eE[CHUNK][3];
        #pragma unroll
        for (int u = 0; u < CHUNK; u++) {
            eE[u][0] = __expf(eb[u * NUM_TAGS + j0]);
            eE[u][1] = __expf(eb[u * NUM_TAGS + j0 + 1]);
            eE[u][2] = __expf(eb[u * NUM_TAGS + j0 + 2]);
        }

        const int4 ma  = ((const int4*)(smask + c * CHUNK))[0];
        const int4 mbq = ((const int4*)(smask + c * CHUNK))[1];
        const int mall = ma.x & ma.y & ma.z & ma.w & mbq.x & mbq.y & mbq.z & mbq.w;

        if (mall) {
            // fast path: fold pending scale into step 0's emission factor
            eE[0][0] *= carry_inv; eE[0][1] *= carry_inv; eE[0][2] *= carry_inv;

            #pragma unroll
            for (int u = 0; u < CHUNK; u++) {
                // alpha load: 24 bf16 = 48 B, all inside one 128-B line
                const uint32_t* wln = &swb16[u & 1][h * 12];
                uint4 A0 = *(const uint4*)(wln);
                uint4 A1 = *(const uint4*)(wln + 4);
                uint4 A2 = *(const uint4*)(wln + 8);
                uint32_t A[12] = {A0.x, A0.y, A0.z, A0.w,
                                  A1.x, A1.y, A1.z, A1.w,
                                  A2.x, A2.y, A2.z, A2.w};

                uint64_t a0[3] = {0,0,0}, a1[3] = {0,0,0};
                #pragma unroll
                for (int k = 0; k < 12; k += 2) {
                    uint64_t Wa = bf2_to_f32x2(A[k]);
                    uint64_t Wb = bf2_to_f32x2(A[k + 1]);
                    #pragma unroll
                    for (int cc = 0; cc < 3; cc++) {
                        fma2(a0[cc], Wa, Ec[cc * 12 + k]);
                        fma2(a1[cc], Wb, Ec[cc * 12 + k + 1]);
                    }
                }
                float d[3];
                #pragma unroll
                for (int cc = 0; cc < 3; cc++) {
                    uint64_t s = add2(a0[cc], a1[cc]);
                    float dd = lo2(s) + hi2(s);                 // own half-dot
                    dd += __shfl_xor_sync(0xffffffffu, dd, 16); // combine halves (commutative)
                    d[cc] = dd * eE[u][cc];
                }
                w0 = d[0]; w1 = d[1]; w2 = d[2];
                uint16_t* wd = (uint16_t*)swb16[(u & 1) ^ 1];
                wd[j0]     = f2bf(w0);     // all lanes store; pair duplicates identical
                wd[j0 + 1] = f2bf(w1);
                wd[j0 + 2] = f2bf(w2);
                asm volatile("" ::: "memory");
            }
        } else {
            // slow path (general mask): apply pending scale, then select-based steps
            w0 *= carry_inv; w1 *= carry_inv; w2 *= carry_inv;
            carry_inv = 1.0f;
            {
                uint16_t* wd = (uint16_t*)swb16[0];
                wd[j0] = f2bf(w0); wd[j0 + 1] = f2bf(w1); wd[j0 + 2] = f2bf(w2);
            }
            __syncwarp();

            #pragma unroll
            for (int u = 0; u < CHUNK; u++) {
                const uint32_t* wln = &swb16[u & 1][h * 12];
                uint4 A0 = *(const uint4*)(wln);
                uint4 A1 = *(const uint4*)(wln + 4);
                uint4 A2 = *(const uint4*)(wln + 8);
                uint32_t A[12] = {A0.x, A0.y, A0.z, A0.w,
                                  A1.x, A1.y, A1.z, A1.w,
                                  A2.x, A2.y, A2.z, A2.w};

                uint64_t a0[3] = {0,0,0}, a1[3] = {0,0,0};
                #pragma unroll
                for (int k = 0; k < 12; k += 2) {
                    uint64_t Wa = bf2_to_f32x2(A[k]);
                    uint64_t Wb = bf2_to_f32x2(A[k + 1]);
                    #pragma unroll
                    for (int cc = 0; cc < 3; cc++) {
                        fma2(a0[cc], Wa, Ec[cc * 12 + k]);
                        fma2(a1[cc], Wb, Ec[cc * 12 + k + 1]);
                    }
                }
                int m = smask[c * CHUNK + u];
                float nv[3];
                #pragma unroll
                for (int cc = 0; cc < 3; cc++) {
                    uint64_t s = add2(a0[cc], a1[cc]);
                    float dd = lo2(s) + hi2(s);
                    dd += __shfl_xor_sync(0xffffffffu, dd, 16);
                    nv[cc] = dd * eE[u][cc];
                }
                w0 = m ? nv[0] : w0;
                w1 = m ? nv[1] : w1;
                w2 = m ? nv[2] : w2;
                uint16_t* wd = (uint16_t*)swb16[(u & 1) ^ 1];
                wd[j0] = f2bf(w0); wd[j0 + 1] = f2bf(w1); wd[j0 + 2] = f2bf(w2);
                __syncwarp();
            }
        }

        // lazy renorm: scale by alpha[0] (>0 always); exact algebra once logged
        float s = __shfl_sync(0xffffffffu, w0, 0);
        C += __logf(s);
        carry_inv = __fdividef(1.0f, s);
    }

    // --- final partition: logZ = C + log( (sum w) * carry_inv ) ------------------------
    float v = (h == 0) ? (w0 + w1 + w2) : 0.0f;
    #pragma unroll
    for (int off = 16; off; off >>= 1)
        v += __shfl_xor_sync(0xffffffffu, v, off);
    if (lane == 0) {
        float logZ  = C + __logf(v * carry_inv);
        float score = sc + em_b[stags[0]];           // emit[0] always counted
        g_nll[b] = logZ - score;
    }

    // --- fused mean-reduce: last CTA does the deterministic sum ------------------------
    unsigned done = 0;
    if (lane == 0) {
        __threadfence();
        done = atomicAdd(&g_count, 1u);
    }
    done = __shfl_sync(0xffffffffu, done, 0);
    if (done == BATCH - 1) {
        __threadfence();
        float r = 0.0f;
        #pragma unroll
        for (int i = lane; i < BATCH; i += 32)
            r += __ldcg(&g_nll[i]);
        #pragma unroll
        for (int off = 16; off; off >>= 1)
            r += __shfl_xor_sync(0xffffffffu, r, off);
        if (lane == 0) {
            out[0] = r * (1.0f / (float)BATCH);
            g_count = 0;   // reset for next graph replay
        }
    }
}

extern "C" void kernel_launch(void* const* d_in, const int* in_sizes, int n_in,
                              void* d_out, int out_size)
{
    const float* emissions   = (const float*)d_in[0];
    const float* transitions = (const float*)d_in[1];
    const int*   tags        = (const int*)d_in[2];
    const int*   mask        = (const int*)d_in[3];
    float*       out         = (float*)d_out;

    crf_fused_kernel<<<BATCH, 32>>>(emissions, transitions, tags, mask, out);
}